// round 6
// baseline (speedup 1.0000x reference)
#include <cuda_runtime.h>

// out = noised + 0.1f * noise   (elementwise, fp32)
// N = 64*3*512*512 = 50,331,648 -> n4 = 12,582,912 float4 (divisible by 1024)
// HBM-streaming: 604 MB traffic. R4 hit 6.83 TB/s (86.2% DRAM). This round:
// 4 float4-pairs per thread (front-batched, MLP=8 LDG.128) + .cs streaming
// hints, grid shrunk 4x to cut wave-transition overhead.

#define VPT 4  // float4s per thread

__global__ void __launch_bounds__(256)
gaussian_noise_add_v4(const float4* __restrict__ noised,
                      const float4* __restrict__ noise,
                      float4* __restrict__ out,
                      int n4)
{
    int base = (blockIdx.x * 256) * VPT + threadIdx.x;

    if (base + (VPT - 1) * 256 < n4) {
        // Fast path: front-batch all 8 loads for max MLP.
        float4 a[VPT], b[VPT];
#pragma unroll
        for (int j = 0; j < VPT; j++)
            a[j] = __ldcs(&noised[base + j * 256]);
#pragma unroll
        for (int j = 0; j < VPT; j++)
            b[j] = __ldcs(&noise[base + j * 256]);
#pragma unroll
        for (int j = 0; j < VPT; j++) {
            float4 r;
            r.x = fmaf(0.1f, b[j].x, a[j].x);
            r.y = fmaf(0.1f, b[j].y, a[j].y);
            r.z = fmaf(0.1f, b[j].z, a[j].z);
            r.w = fmaf(0.1f, b[j].w, a[j].w);
            __stcs(&out[base + j * 256], r);
        }
    } else {
        // Guarded remainder (not taken for this problem's shape).
#pragma unroll
        for (int j = 0; j < VPT; j++) {
            int i = base + j * 256;
            if (i < n4) {
                float4 a = __ldcs(&noised[i]);
                float4 b = __ldcs(&noise[i]);
                float4 r;
                r.x = fmaf(0.1f, b.x, a.x);
                r.y = fmaf(0.1f, b.y, a.y);
                r.z = fmaf(0.1f, b.z, a.z);
                r.w = fmaf(0.1f, b.w, a.w);
                __stcs(&out[i], r);
            }
        }
    }
}

// Scalar tail for n not divisible by 4 (not launched for this shape).
__global__ void gaussian_noise_tail_kernel(const float* __restrict__ noised,
                                           const float* __restrict__ noise,
                                           float* __restrict__ out,
                                           int start, int n)
{
    int i = start + blockIdx.x * blockDim.x + threadIdx.x;
    if (i < n) {
        out[i] = fmaf(0.1f, noise[i], noised[i]);
    }
}

extern "C" void kernel_launch(void* const* d_in, const int* in_sizes, int n_in,
                              void* d_out, int out_size)
{
    const float* noised = (const float*)d_in[0];
    const float* noise  = (const float*)d_in[1];
    float* out = (float*)d_out;
    int n = in_sizes[0];

    int n4 = n >> 2;
    if (n4 > 0) {
        const int threads = 256;
        const int per_block = threads * VPT;
        int blocks = (n4 + per_block - 1) / per_block;
        gaussian_noise_add_v4<<<blocks, threads>>>(
            (const float4*)noised, (const float4*)noise, (float4*)out, n4);
    }
    int rem = n - (n4 << 2);
    if (rem > 0) {
        gaussian_noise_tail_kernel<<<1, 256>>>(noised, noise, out, n4 << 2, n);
    }
}